// round 4
// baseline (speedup 1.0000x reference)
#include <cuda_runtime.h>

#define HIDDEN    128
#define MAX_NODES 100000
#define NCOMBINE_BLOCKS 65   // 65 blocks * 8 warps = 520 warps >= 515 tasks

// Scratch (device globals; allocation is forbidden).
__device__ float4 g_P[MAX_NODES];      // {n·A0, n·A1, n·B0, n·B1} per node
__device__ float4 g_A0v[32], g_A1v[32], g_B0v[32], g_B1v[32];  // collapsed weights
__device__ float  g_bc[2];
__device__ int    g_is64;
__device__ int    g_done = 0;          // combine-completion counter
__device__ int    g_flag = 0;          // combine-ready flag (reset by edge_kernel)

// ---------------------------------------------------------------------------
// Fused kernel: blocks 0..64 collapse W1@W2 -> Wc (256x2) + bc + dtype probe,
// signal via g_flag. ALL blocks prefetch their feature rows into registers
// BEFORE spinning, so the 51.2 MB HBM stream overlaps the combine phase.
// Then each warp computes 4 nodes' projections {n*A0, n*A1, n*B0, n*B1}.
// ---------------------------------------------------------------------------
#define NODES_PER_WARP  4
#define WARPS_PER_BLOCK 8
#define NODES_PER_BLOCK (NODES_PER_WARP * WARPS_PER_BLOCK)   // 32

__global__ void __launch_bounds__(256) fused_kernel(const float* __restrict__ feat,
                                                    const float* __restrict__ W1,
                                                    const float* __restrict__ b1,
                                                    const float* __restrict__ W2,
                                                    const float* __restrict__ b2,
                                                    const long long* __restrict__ edges_as_i64,
                                                    int n_edges, int n_nodes)
{
    int tid  = threadIdx.x;
    int warp = tid >> 5;
    int lane = tid & 31;

    // ---- Phase A (blocks 0..64 only): collapse the two linear layers ----
    if (blockIdx.x < NCOMBINE_BLOCKS) {
        int gw = blockIdx.x * WARPS_PER_BLOCK + warp;
        if (gw < 512) {
            // Wc[i][j] = sum_k W1[i][k] * W2[k][j], i in [0,256), j in {0,1}
            int i = gw >> 1;
            int j = gw & 1;
            float acc = 0.f;
            #pragma unroll
            for (int k = lane; k < 4 * HIDDEN; k += 32)
                acc += W1[i * (4 * HIDDEN) + k] * W2[k * 2 + j];
            #pragma unroll
            for (int o = 16; o; o >>= 1) acc += __shfl_xor_sync(0xffffffffu, acc, o);
            if (lane == 0) {
                float* dst = (float*)((i < HIDDEN) ? (j ? g_A1v : g_A0v)
                                                   : (j ? g_B1v : g_B0v));
                dst[i & (HIDDEN - 1)] = acc;
            }
        } else if (gw < 514) {
            int j = gw - 512;
            float acc = 0.f;
            #pragma unroll
            for (int k = lane; k < 4 * HIDDEN; k += 32)
                acc += b1[k] * W2[k * 2 + j];
            #pragma unroll
            for (int o = 16; o; o >>= 1) acc += __shfl_xor_sync(0xffffffffu, acc, o);
            if (lane == 0) g_bc[j] = acc + b2[j];
        } else if (gw == 514) {
            // Warp-parallel dtype probe: int32 data read as int64 pairs fails
            // the [0, MAX_NODES) range check almost surely over 64 samples.
            int ok = 1;
            #pragma unroll
            for (int r = 0; r < 2; ++r) {
                int t = r * 32 + lane;
                if (t < n_edges) {
                    long long v = edges_as_i64[t];
                    if (v < 0 || v >= (long long)MAX_NODES) ok = 0;
                }
            }
            ok = __all_sync(0xffffffffu, ok);
            if (lane == 0) g_is64 = ok;
        }
        __syncthreads();
        if (tid == 0) {
            __threadfence();                               // publish weights
            if (atomicAdd(&g_done, 1) == NCOMBINE_BLOCKS - 1)
                *(volatile int*)&g_flag = 1;               // release
        }
    }

    // ---- Phase B (all blocks): node projections ----
    int node0 = blockIdx.x * NODES_PER_BLOCK + warp * NODES_PER_WARP;

    // Prefetch feature rows BEFORE the spin: the HBM stream starts immediately.
    float4 x[NODES_PER_WARP];
    #pragma unroll
    for (int r = 0; r < NODES_PER_WARP; ++r) {
        int node = node0 + r;
        if (node < n_nodes)
            x[r] = reinterpret_cast<const float4*>(feat + (size_t)node * HIDDEN)[lane];
    }

    // Wait for collapsed weights (combine blocks have the lowest bids -> wave 1).
    if (*(volatile int*)&g_flag == 0) {
        while (*(volatile int*)&g_flag == 0) __nanosleep(64);
    }
    __threadfence();                                       // acquire

    float4 wa0 = g_A0v[lane];
    float4 wa1 = g_A1v[lane];
    float4 wb0 = g_B0v[lane];
    float4 wb1 = g_B1v[lane];

    #pragma unroll
    for (int r = 0; r < NODES_PER_WARP; ++r) {
        int node = node0 + r;
        if (node >= n_nodes) break;
        float a0 = x[r].x * wa0.x + x[r].y * wa0.y + x[r].z * wa0.z + x[r].w * wa0.w;
        float a1 = x[r].x * wa1.x + x[r].y * wa1.y + x[r].z * wa1.z + x[r].w * wa1.w;
        float c0 = x[r].x * wb0.x + x[r].y * wb0.y + x[r].z * wb0.z + x[r].w * wb0.w;
        float c1 = x[r].x * wb1.x + x[r].y * wb1.y + x[r].z * wb1.z + x[r].w * wb1.w;
        #pragma unroll
        for (int o = 16; o; o >>= 1) {
            a0 += __shfl_xor_sync(0xffffffffu, a0, o);
            a1 += __shfl_xor_sync(0xffffffffu, a1, o);
            c0 += __shfl_xor_sync(0xffffffffu, c0, o);
            c1 += __shfl_xor_sync(0xffffffffu, c1, o);
        }
        if (lane == 0) g_P[node] = make_float4(a0, a1, c0, c1);
    }
}

// ---------------------------------------------------------------------------
// Edge kernel: 2 edges per thread, 16B index loads + 16B output store.
// g_P (1.6 MB) is L2-resident -> gathers are L2 hits. Also resets the
// fused-kernel flags for the next graph replay (runs strictly after).
// ---------------------------------------------------------------------------
__global__ void __launch_bounds__(256) edge_kernel(const void* __restrict__ edges,
                                                   float4* __restrict__ out4,
                                                   int n_edges)
{
    if (blockIdx.x == 0 && threadIdx.x == 0) { g_flag = 0; g_done = 0; }

    int p  = blockIdx.x * blockDim.x + threadIdx.x;
    int np = n_edges >> 1;
    float bc0 = g_bc[0], bc1 = g_bc[1];

    if (p < np) {
        int s0, s1, d0, d1;
        if (g_is64) {
            const longlong2* E = (const longlong2*)edges;
            longlong2 s = E[p];        // edges[2p], edges[2p+1]
            longlong2 d = E[np + p];   // edges[n_edges+2p], +1 (n_edges even)
            s0 = (int)s.x; s1 = (int)s.y; d0 = (int)d.x; d1 = (int)d.y;
        } else {
            const int2* E = (const int2*)edges;
            int2 s = E[p];
            int2 d = E[np + p];
            s0 = s.x; s1 = s.y; d0 = d.x; d1 = d.y;
        }
        float4 ps0 = __ldg(&g_P[s0]);
        float4 ps1 = __ldg(&g_P[s1]);
        float4 pd0 = __ldg(&g_P[d0]);
        float4 pd1 = __ldg(&g_P[d1]);

        float l00 = ps0.x + pd0.z + bc0, l01 = ps0.y + pd0.w + bc1;
        float l10 = ps1.x + pd1.z + bc0, l11 = ps1.y + pd1.w + bc1;

        // softmax over 2 classes == sigmoid of the logit gap
        float q0 = 1.0f / (1.0f + __expf(l00 - l01));   // prob class 1, edge 0
        float q1 = 1.0f / (1.0f + __expf(l10 - l11));   // prob class 1, edge 1
        out4[p] = make_float4(1.0f - q0, q0, 1.0f - q1, q1);
    } else if ((n_edges & 1) && p == np) {
        // odd tail: last edge
        int e = n_edges - 1;
        int s, d;
        if (g_is64) {
            const long long* E = (const long long*)edges;
            s = (int)E[e]; d = (int)E[e + n_edges];
        } else {
            const int* E = (const int*)edges;
            s = E[e]; d = E[e + n_edges];
        }
        float4 ps = __ldg(&g_P[s]);
        float4 pd = __ldg(&g_P[d]);
        float l0 = ps.x + pd.z + bc0, l1 = ps.y + pd.w + bc1;
        float q = 1.0f / (1.0f + __expf(l0 - l1));
        ((float2*)out4)[e] = make_float2(1.0f - q, q);
    }
}

// ---------------------------------------------------------------------------
// Launch. metadata order:
//   0: node_features_after_gcn (float32, N_NODES*128)
//   1: edges                   (int64 or int32, 2*N_EDGES)
//   2: W1 (256*512)  3: b1 (512)  4: W2 (512*2)  5: b2 (2)
// ---------------------------------------------------------------------------
extern "C" void kernel_launch(void* const* d_in, const int* in_sizes, int n_in,
                              void* d_out, int out_size)
{
    const float* feat  = (const float*)d_in[0];
    const void*  edges = d_in[1];
    const float* W1    = (const float*)d_in[2];
    const float* b1    = (const float*)d_in[3];
    const float* W2    = (const float*)d_in[4];
    const float* b2    = (const float*)d_in[5];

    int n_nodes = in_sizes[0] / HIDDEN;
    if (n_nodes > MAX_NODES) n_nodes = MAX_NODES;
    int n_edges = in_sizes[1] / 2;

    int nblocks = (n_nodes + NODES_PER_BLOCK - 1) / NODES_PER_BLOCK;
    if (nblocks < NCOMBINE_BLOCKS) nblocks = NCOMBINE_BLOCKS;

    fused_kernel<<<nblocks, 256>>>(feat, W1, b1, W2, b2,
                                   (const long long*)edges, n_edges, n_nodes);

    int pair_threads = (n_edges >> 1) + (n_edges & 1);
    edge_kernel<<<(pair_threads + 255) / 256, 256>>>(edges, (float4*)d_out, n_edges);
}

// round 6
// speedup vs baseline: 1.5684x; 1.5684x over previous
#include <cuda_runtime.h>

#define HIDDEN    128
#define MAX_NODES 100000

// Scratch (device globals; allocation is forbidden).
// Gap form: output depends only on l0-l1, so per node we keep ONE float per
// role:  gs[n] = n·dA,  gd[n] = n·dB,  where dA/dB = W1 halves @ (w2_0 - w2_1).
__device__ float  g_GS[MAX_NODES];
__device__ float  g_GD[MAX_NODES];
__device__ float4 g_dAv[32], g_dBv[32];   // dA, dB as 32 x float4
__device__ float  g_gapb;                 // b1·(w2_0-w2_1) + b2_0 - b2_1
__device__ int    g_is64;

// ---------------------------------------------------------------------------
// Kernel A: collapse both linear layers into the gap direction.
//   dA[i] = sum_k W1[i][k]      * (W2[k][0]-W2[k][1])   i in [0,128)
//   dB[i] = sum_k W1[128+i][k]  * (W2[k][0]-W2[k][1])
// One warp per row (256 rows) + bias warp + dtype-probe warp. 33 blocks.
// ---------------------------------------------------------------------------
__global__ void __launch_bounds__(256) combine_kernel(
        const float* __restrict__ W1, const float* __restrict__ b1,
        const float* __restrict__ W2, const float* __restrict__ b2,
        const long long* __restrict__ edges_as_i64, int n_edges)
{
    int warp = (blockIdx.x * blockDim.x + threadIdx.x) >> 5;
    int lane = threadIdx.x & 31;

    if (warp < 256) {
        int i = warp;
        float acc = 0.f;
        #pragma unroll
        for (int k = lane; k < 4 * HIDDEN; k += 32)
            acc += W1[i * (4 * HIDDEN) + k] * (W2[2 * k] - W2[2 * k + 1]);
        #pragma unroll
        for (int o = 16; o; o >>= 1) acc += __shfl_xor_sync(0xffffffffu, acc, o);
        if (lane == 0) {
            float* dst = (i < HIDDEN) ? (float*)g_dAv : (float*)g_dBv;
            dst[i & (HIDDEN - 1)] = acc;
        }
    } else if (warp == 256) {
        float acc = 0.f;
        #pragma unroll
        for (int k = lane; k < 4 * HIDDEN; k += 32)
            acc += b1[k] * (W2[2 * k] - W2[2 * k + 1]);
        #pragma unroll
        for (int o = 16; o; o >>= 1) acc += __shfl_xor_sync(0xffffffffu, acc, o);
        if (lane == 0) g_gapb = acc + b2[0] - b2[1];
    } else if (warp == 257) {
        // Warp-parallel dtype probe: an int32 buffer misread as int64 pairs
        // fails the [0, MAX_NODES) range check almost surely over 64 samples.
        int ok = 1;
        #pragma unroll
        for (int r = 0; r < 2; ++r) {
            int t = r * 32 + lane;
            if (t < n_edges) {
                long long v = edges_as_i64[t];
                if (v < 0 || v >= (long long)MAX_NODES) ok = 0;
            }
        }
        ok = __all_sync(0xffffffffu, ok);
        if (lane == 0) g_is64 = ok;
    }
}

// ---------------------------------------------------------------------------
// Kernel B: per-node gap projections. 8 nodes per warp, all row loads
// front-batched (MLP_p1=8). Streams 51.2 MB of features once.
// ---------------------------------------------------------------------------
#define NODES_PER_WARP  8
#define WARPS_PER_BLOCK 8
#define NODES_PER_BLOCK (NODES_PER_WARP * WARPS_PER_BLOCK)   // 64

__global__ void __launch_bounds__(256) node_kernel(const float* __restrict__ feat,
                                                   int n_nodes)
{
    int warp = threadIdx.x >> 5;
    int lane = threadIdx.x & 31;
    int node0 = blockIdx.x * NODES_PER_BLOCK + warp * NODES_PER_WARP;

    float4 x[NODES_PER_WARP];
    #pragma unroll
    for (int r = 0; r < NODES_PER_WARP; ++r) {
        int node = node0 + r;
        if (node < n_nodes)
            x[r] = reinterpret_cast<const float4*>(feat + (size_t)node * HIDDEN)[lane];
    }

    float4 wa = g_dAv[lane];   // broadcast-friendly (uniform per lane, cached)
    float4 wb = g_dBv[lane];

    #pragma unroll
    for (int r = 0; r < NODES_PER_WARP; ++r) {
        int node = node0 + r;
        if (node >= n_nodes) break;
        float gs = x[r].x * wa.x + x[r].y * wa.y + x[r].z * wa.z + x[r].w * wa.w;
        float gd = x[r].x * wb.x + x[r].y * wb.y + x[r].z * wb.z + x[r].w * wb.w;
        #pragma unroll
        for (int o = 16; o; o >>= 1) {
            gs += __shfl_xor_sync(0xffffffffu, gs, o);
            gd += __shfl_xor_sync(0xffffffffu, gd, o);
        }
        if (lane == 0) {
            g_GS[node] = gs;
            g_GD[node] = gd;
        }
    }
}

// ---------------------------------------------------------------------------
// Kernel C: 4 edges per thread. Gathers are 4-byte loads from two 400 KB
// L2-resident tables (8 independent LDG.32 in flight per thread).
//   gap = gs[s] + gd[d] + gapb = l0 - l1
//   p1  = 1/(1+exp(gap)),  out = (1-p1, p1)
// ---------------------------------------------------------------------------
#define EDGES_PER_THREAD 4

__global__ void __launch_bounds__(256) edge_kernel(const void* __restrict__ edges,
                                                   float2* __restrict__ out,
                                                   int n_edges)
{
    int t = blockIdx.x * blockDim.x + threadIdx.x;
    int base = t * EDGES_PER_THREAD;
    if (base >= n_edges) return;

    float gapb = g_gapb;
    int is64 = g_is64;

    int s[EDGES_PER_THREAD], d[EDGES_PER_THREAD];

    if (base + EDGES_PER_THREAD <= n_edges) {
        if (is64) {
            const longlong2* E = (const longlong2*)edges;
            longlong2 s01 = E[(base >> 1)];
            longlong2 s23 = E[(base >> 1) + 1];
            longlong2 d01 = E[((n_edges + base) >> 1)];
            longlong2 d23 = E[((n_edges + base) >> 1) + 1];
            s[0] = (int)s01.x; s[1] = (int)s01.y; s[2] = (int)s23.x; s[3] = (int)s23.y;
            d[0] = (int)d01.x; d[1] = (int)d01.y; d[2] = (int)d23.x; d[3] = (int)d23.y;
        } else {
            const int4* E = (const int4*)edges;
            int4 sv = E[base >> 2];
            int4 dv = E[(n_edges + base) >> 2];
            s[0] = sv.x; s[1] = sv.y; s[2] = sv.z; s[3] = sv.w;
            d[0] = dv.x; d[1] = dv.y; d[2] = dv.z; d[3] = dv.w;
        }

        float gs[EDGES_PER_THREAD], gd[EDGES_PER_THREAD];
        #pragma unroll
        for (int r = 0; r < EDGES_PER_THREAD; ++r) gs[r] = __ldg(&g_GS[s[r]]);
        #pragma unroll
        for (int r = 0; r < EDGES_PER_THREAD; ++r) gd[r] = __ldg(&g_GD[d[r]]);

        float p1[EDGES_PER_THREAD];
        #pragma unroll
        for (int r = 0; r < EDGES_PER_THREAD; ++r)
            p1[r] = 1.0f / (1.0f + __expf(gs[r] + gd[r] + gapb));

        float4* o4 = (float4*)(out + base);   // 32B aligned (base % 4 == 0)
        o4[0] = make_float4(1.0f - p1[0], p1[0], 1.0f - p1[1], p1[1]);
        o4[1] = make_float4(1.0f - p1[2], p1[2], 1.0f - p1[3], p1[3]);
    } else {
        // Tail: scalar per edge.
        for (int e = base; e < n_edges; ++e) {
            int si, di;
            if (is64) {
                const long long* E = (const long long*)edges;
                si = (int)E[e]; di = (int)E[e + n_edges];
            } else {
                const int* E = (const int*)edges;
                si = E[e]; di = E[e + n_edges];
            }
            float p = 1.0f / (1.0f + __expf(__ldg(&g_GS[si]) + __ldg(&g_GD[di]) + gapb));
            out[e] = make_float2(1.0f - p, p);
        }
    }
}

// ---------------------------------------------------------------------------
// Launch. metadata order:
//   0: node_features_after_gcn (float32, N_NODES*128)
//   1: edges                   (int64 or int32, 2*N_EDGES)
//   2: W1 (256*512)  3: b1 (512)  4: W2 (512*2)  5: b2 (2)
// ---------------------------------------------------------------------------
extern "C" void kernel_launch(void* const* d_in, const int* in_sizes, int n_in,
                              void* d_out, int out_size)
{
    const float* feat  = (const float*)d_in[0];
    const void*  edges = d_in[1];
    const float* W1    = (const float*)d_in[2];
    const float* b1    = (const float*)d_in[3];
    const float* W2    = (const float*)d_in[4];
    const float* b2    = (const float*)d_in[5];

    int n_nodes = in_sizes[0] / HIDDEN;
    if (n_nodes > MAX_NODES) n_nodes = MAX_NODES;
    int n_edges = in_sizes[1] / 2;

    // A: 258 warps -> 33 blocks of 256.
    combine_kernel<<<33, 256>>>(W1, b1, W2, b2, (const long long*)edges, n_edges);

    // B: 64 nodes per block.
    node_kernel<<<(n_nodes + NODES_PER_BLOCK - 1) / NODES_PER_BLOCK, 256>>>(feat, n_nodes);

    // C: 4 edges per thread.
    int nthreads = (n_edges + EDGES_PER_THREAD - 1) / EDGES_PER_THREAD;
    edge_kernel<<<(nthreads + 255) / 256, 256>>>(edges, (float2*)d_out, n_edges);
}